// round 11
// baseline (speedup 1.0000x reference)
#include <cuda_runtime.h>
#include <math.h>

#define T_STEPS 8192
#define HID     1024
#define IN_K    2048
#define NGATE   3072
#define NCTA    128

#define BM 128
#define BN 128
#define BK 16
#define NMB   (T_STEPS / BM)          // 64 m-blocks
#define NTPB  (NGATE / BN)            // 24 n-tiles per m-block
#define NGEMM (NMB * NTPB)            // 1536 gemm CTAs

// ---- device scratch (allocation-free: __device__ globals) ----
__device__ float g_gi[(size_t)T_STEPS * NGATE];      // ~100.7 MB input gates
__device__ float g_wt[(size_t)NGATE * IN_K];          // 25 MB repacked aligned W
__device__ float g_hv[2][HID];                        // double-buffered h
__device__ unsigned g_ctr;                            // scan step counter
__device__ unsigned g_blkdone[NMB];                   // per-m-block gi readiness

// =====================================================================
// Kernel 0: repack w_ih[:, :2048] into aligned g_wt; reset counters.
// =====================================================================
__global__ void repack_w(const float* __restrict__ w_ih)
{
    if (blockIdx.x == 0) {
        if (threadIdx.x == 0) g_ctr = 0u;
        if (threadIdx.x < NMB) g_blkdone[threadIdx.x] = 0u;
    }
    const size_t i = (size_t)blockIdx.x * blockDim.x + threadIdx.x;
    const size_t total = (size_t)NGATE * IN_K;
    for (size_t x = i; x < total; x += (size_t)gridDim.x * blockDim.x) {
        const size_t n = x >> 11;
        const size_t k = x & 2047;
        g_wt[x] = w_ih[n * 2049 + k];
    }
}

// =====================================================================
// Fused kernel: bid 0..127 = persistent scan CTAs (R10 protocol);
// bid 128..1663 = GEMM tile CTAs, highest-t m-blocks first, signalling
// per-block readiness via release-counters. launch_bounds(256,2) forces
// <=128 regs so one scan CTA + one gemm CTA co-reside per SM.
// =====================================================================
__device__ __forceinline__ float sigmoidf_(float x)
{
    return __fdividef(1.f, 1.f + __expf(-x));
}
__device__ __forceinline__ float tanhf_(float x)
{
    float ax = fabsf(x);
    float e  = __expf(-2.f * ax);
    float t  = __fdividef(1.f - e, 1.f + e);
    return copysignf(t, x);
}

__global__ void __launch_bounds__(256, 2) fused(
    const float* __restrict__ feat,   // [8192, 2048]
    const float* __restrict__ rew,    // [8192]
    const float* __restrict__ w_ih,   // [3072, 2049]
    const float* __restrict__ b_ih,   // [3072]
    const float* __restrict__ w_hh,   // [3072, 1024]
    const float* __restrict__ b_hh,   // [3072]
    float* __restrict__ out)          // [1024]
{
    __shared__ float As[BK][BM];
    __shared__ float Ws[BK][BN];
    __shared__ float h_sm[HID];

    const int tid = threadIdx.x;

    if (blockIdx.x >= NCTA) {
        // ================= GEMM tile CTA =================
        const int g     = blockIdx.x - NCTA;
        const int mb    = (NMB - 1) - g / NTPB;   // descending t-blocks first
        const int nBase = (g % NTPB) * BN;
        const int mBase = mb * BM;
        const int tx = tid & 15;
        const int ty = tid >> 4;

        float acc[8][8];
        #pragma unroll
        for (int i = 0; i < 8; i++)
            #pragma unroll
            for (int j = 0; j < 8; j++) acc[i][j] = 0.f;

        for (int kB = 0; kB < IN_K; kB += BK) {
            #pragma unroll
            for (int v = 0; v < 2; v++) {
                int f   = tid + v * 256;
                int row = f >> 2;
                int kq  = (f & 3) << 2;
                float4 a = *reinterpret_cast<const float4*>(
                    &feat[(size_t)(mBase + row) * IN_K + kB + kq]);
                As[kq + 0][row] = a.x;
                As[kq + 1][row] = a.y;
                As[kq + 2][row] = a.z;
                As[kq + 3][row] = a.w;
            }
            #pragma unroll
            for (int v = 0; v < 2; v++) {
                int f   = tid + v * 256;
                int row = f >> 2;
                int kq  = (f & 3) << 2;
                float4 b = *reinterpret_cast<const float4*>(
                    &g_wt[(size_t)(nBase + row) * IN_K + kB + kq]);
                Ws[kq + 0][row] = b.x;
                Ws[kq + 1][row] = b.y;
                Ws[kq + 2][row] = b.z;
                Ws[kq + 3][row] = b.w;
            }
            __syncthreads();

            #pragma unroll
            for (int k = 0; k < BK; k++) {
                float a[8], b[8];
                float4 a0 = *reinterpret_cast<const float4*>(&As[k][ty * 8 + 0]);
                float4 a1 = *reinterpret_cast<const float4*>(&As[k][ty * 8 + 4]);
                float4 b0 = *reinterpret_cast<const float4*>(&Ws[k][tx * 8 + 0]);
                float4 b1 = *reinterpret_cast<const float4*>(&Ws[k][tx * 8 + 4]);
                a[0]=a0.x; a[1]=a0.y; a[2]=a0.z; a[3]=a0.w;
                a[4]=a1.x; a[5]=a1.y; a[6]=a1.z; a[7]=a1.w;
                b[0]=b0.x; b[1]=b0.y; b[2]=b0.z; b[3]=b0.w;
                b[4]=b1.x; b[5]=b1.y; b[6]=b1.z; b[7]=b1.w;
                #pragma unroll
                for (int i = 0; i < 8; i++)
                    #pragma unroll
                    for (int j = 0; j < 8; j++)
                        acc[i][j] = fmaf(a[i], b[j], acc[i][j]);
            }
            __syncthreads();
        }

        float rw[8], wl[8], bb[8];
        #pragma unroll
        for (int i = 0; i < 8; i++) rw[i] = rew[mBase + ty * 8 + i];
        #pragma unroll
        for (int j = 0; j < 8; j++) {
            int n = nBase + tx * 8 + j;
            wl[j] = w_ih[(size_t)n * 2049 + 2048];
            bb[j] = b_ih[n];
        }
        #pragma unroll
        for (int i = 0; i < 8; i++) {
            int m = mBase + ty * 8 + i;
            #pragma unroll
            for (int j = 0; j < 8; j++) {
                int n = nBase + tx * 8 + j;
                g_gi[(size_t)m * NGATE + n] = acc[i][j] + rw[i] * wl[j] + bb[j];
            }
        }
        __syncthreads();   // all tile stores done, CTA-ordered before release
        if (tid == 0)
            asm volatile("red.release.gpu.global.add.u32 [%0], %1;"
                         :: "l"(&g_blkdone[mb]), "r"(1u) : "memory");
        return;
    }

    // ================= persistent scan CTA =================
    const int c = blockIdx.x;
    const int w = tid >> 5;
    const int l = tid & 31;
    const int u = c * 8 + w;

    // register-resident recurrent weights: lane l holds k = l + 32j
    float wr[32], wz[32], wn[32];
    {
        const float* pr = w_hh + (size_t)(          u) * HID + l;
        const float* pz = w_hh + (size_t)(HID     + u) * HID + l;
        const float* pn = w_hh + (size_t)(2 * HID + u) * HID + l;
        #pragma unroll
        for (int j = 0; j < 32; j++) {
            wr[j] = pr[32 * j];
            wz[j] = pz[32 * j];
            wn[j] = pn[32 * j];
        }
    }
    const float bhr = b_hh[u];
    const float bhz = b_hh[HID + u];
    const float bhn = b_hh[2 * HID + u];

    // h^0 = 0
    {
        float4 z4 = make_float4(0.f, 0.f, 0.f, 0.f);
        *reinterpret_cast<float4*>(&h_sm[tid * 4]) = z4;
    }
    float hval = 0.f;

    unsigned* ctrp = &g_ctr;

    // gate: block 63 (rows 8064..8191) must be fully written
    if (tid == 0) {
        unsigned v;
        do {
            asm volatile("ld.acquire.gpu.global.u32 %0, [%1];"
                         : "=r"(v) : "l"(&g_blkdone[NMB - 1]) : "memory");
        } while (v < (unsigned)NTPB);
    }
    __syncthreads();

    // prefetch gi for step 0 (t = T-1); ldcg: gi written this kernel
    const float* gp0 = g_gi + (size_t)(T_STEPS - 1) * NGATE + u;
    float gir = __ldcg(gp0), giz = __ldcg(gp0 + HID), gin = __ldcg(gp0 + 2 * HID);

    for (int s = 0; s < T_STEPS; s++) {
        const int t = T_STEPS - 1 - s;   // reverse scan
        // prefetch NEXT step's gi (gated at block boundaries)
        float girN = 0.f, gizN = 0.f, ginN = 0.f;
        if (s + 1 < T_STEPS) {
            if ((t & (BM - 1)) == 0) {   // row t-1 enters a new (lower) block
                if (tid == 0) {
                    unsigned v;
                    do {
                        asm volatile("ld.acquire.gpu.global.u32 %0, [%1];"
                                     : "=r"(v) : "l"(&g_blkdone[(t - 1) >> 7]) : "memory");
                    } while (v < (unsigned)NTPB);
                }
                __syncthreads();
            }
            const float* gp = g_gi + (size_t)(t - 1) * NGATE + u;
            girN = __ldcg(gp);
            gizN = __ldcg(gp + HID);
            ginN = __ldcg(gp + 2 * HID);
        }

        if (s > 0) {
            if (tid == 0) {
                const unsigned target = (unsigned)s * (unsigned)NCTA;
                unsigned f;
                do {
                    asm volatile("ld.acquire.gpu.global.u32 %0, [%1];"
                                 : "=r"(f) : "l"(ctrp) : "memory");
                } while (f < target);
            }
            __syncthreads();   // (A) barrier observed
            float4 hv4;
            asm volatile("ld.global.cg.v4.f32 {%0,%1,%2,%3}, [%4];"
                         : "=f"(hv4.x), "=f"(hv4.y), "=f"(hv4.z), "=f"(hv4.w)
                         : "l"(&g_hv[s & 1][tid * 4]) : "memory");
            *reinterpret_cast<float4*>(&h_sm[tid * 4]) = hv4;
        }
        __syncthreads();   // (B) h staged in smem

        float dr = 0.f, dz = 0.f, dn = 0.f;
        #pragma unroll
        for (int j = 0; j < 32; j++) {
            const float h = h_sm[l + 32 * j];
            dr = fmaf(wr[j], h, dr);
            dz = fmaf(wz[j], h, dz);
            dn = fmaf(wn[j], h, dn);
        }
        #pragma unroll
        for (int o = 16; o > 0; o >>= 1) {
            dr += __shfl_xor_sync(0xffffffffu, dr, o);
            dz += __shfl_xor_sync(0xffffffffu, dz, o);
            dn += __shfl_xor_sync(0xffffffffu, dn, o);
        }

        const float r = sigmoidf_(gir + dr + bhr);
        const float z = sigmoidf_(giz + dz + bhz);
        const float n = tanhf_(gin + r * (dn + bhn));
        hval = (1.f - z) * n + z * hval;

        if (s < T_STEPS - 1) {
            if (l == 0)
                asm volatile("st.global.cg.f32 [%0], %1;"
                             :: "l"(&g_hv[(s + 1) & 1][u]), "f"(hval) : "memory");
            __syncthreads();   // (C) publishes drained, CTA-ordered before release
            if (tid == 0)
                asm volatile("red.release.gpu.global.add.u32 [%0], %1;"
                             :: "l"(ctrp), "r"(1u) : "memory");
        }

        gir = girN; giz = gizN; gin = ginN;
    }

    if (l == 0) out[u] = hval;
}

// =====================================================================
extern "C" void kernel_launch(void* const* d_in, const int* in_sizes, int n_in,
                              void* d_out, int out_size)
{
    const float* feat = (const float*)d_in[0];   // [8192, 2048]
    const float* rew  = (const float*)d_in[1];   // [8192]
    const float* w_ih = (const float*)d_in[2];   // [3072, 2049]
    const float* w_hh = (const float*)d_in[3];   // [3072, 1024]
    const float* b_ih = (const float*)d_in[4];   // [3072]
    const float* b_hh = (const float*)d_in[5];   // [3072]
    float* out = (float*)d_out;                  // [1, 1024]

    repack_w<<<592, 256>>>(w_ih);
    fused<<<NCTA + NGEMM, 256>>>(feat, rew, w_ih, b_ih, w_hh, b_hh, out);
}

// round 12
// speedup vs baseline: 1.0430x; 1.0430x over previous
#include <cuda_runtime.h>
#include <math.h>

#define T_STEPS 8192
#define HID     1024
#define IN_K    2048
#define NGATE   3072
#define NCTA    128

// ---- device scratch (allocation-free: __device__ globals) ----
__device__ float g_gi[(size_t)T_STEPS * NGATE];      // ~100.7 MB precomputed input gates
__device__ float g_wt[(size_t)NGATE * IN_K];          // 25 MB: w_ih[:, :2048] repacked, aligned stride 2048
__device__ float g_hv[2][HID];                        // double-buffered h
__device__ unsigned g_ctr;                            // monotonic step counter (release/acquire, GPU scope)

// =====================================================================
// Kernel 0: repack w_ih[:, :2048] (row stride 2049, misaligned) into
// g_wt (row stride 2048, float4-aligned). Also resets the scan counter.
// =====================================================================
__global__ void repack_w(const float* __restrict__ w_ih)
{
    if (blockIdx.x == 0 && threadIdx.x == 0) g_ctr = 0u;
    const size_t i = (size_t)blockIdx.x * blockDim.x + threadIdx.x;
    const size_t total = (size_t)NGATE * IN_K;
    for (size_t x = i; x < total; x += (size_t)gridDim.x * blockDim.x) {
        const size_t n = x >> 11;           // / 2048
        const size_t k = x & 2047;          // % 2048
        g_wt[x] = w_ih[n * 2049 + k];
    }
}

// =====================================================================
// Kernel 1: gi = features @ w_t^T + rewards * w_ih[:,2048] + b_ih
// fp32 SIMT tiled GEMM, BM=BN=128, BK=16, 8x8 per thread, 2 CTAs/SM.
// (R10 version, known good.)
// =====================================================================
#define BM 128
#define BN 128
#define BK 16

__global__ void __launch_bounds__(256, 2) gi_gemm(
    const float* __restrict__ feat,   // [8192, 2048]
    const float* __restrict__ rew,    // [8192]
    const float* __restrict__ w_ih,   // [3072, 2049] (only col 2048 + epilogue use)
    const float* __restrict__ b_ih)   // [3072]
{
    __shared__ float As[BK][BM];
    __shared__ float Ws[BK][BN];

    const int tid   = threadIdx.x;
    const int nBase = blockIdx.x * BN;
    const int mBase = blockIdx.y * BM;
    const int tx = tid & 15;          // n direction
    const int ty = tid >> 4;          // m direction

    float acc[8][8];
    #pragma unroll
    for (int i = 0; i < 8; i++)
        #pragma unroll
        for (int j = 0; j < 8; j++) acc[i][j] = 0.f;

    for (int kB = 0; kB < IN_K; kB += BK) {
        #pragma unroll
        for (int v = 0; v < 2; v++) {
            int f   = tid + v * 256;            // 0..511
            int row = f >> 2;
            int kq  = (f & 3) << 2;
            float4 a = *reinterpret_cast<const float4*>(
                &feat[(size_t)(mBase + row) * IN_K + kB + kq]);
            As[kq + 0][row] = a.x;
            As[kq + 1][row] = a.y;
            As[kq + 2][row] = a.z;
            As[kq + 3][row] = a.w;
        }
        #pragma unroll
        for (int v = 0; v < 2; v++) {
            int f   = tid + v * 256;            // 0..511
            int row = f >> 2;
            int kq  = (f & 3) << 2;
            float4 b = *reinterpret_cast<const float4*>(
                &g_wt[(size_t)(nBase + row) * IN_K + kB + kq]);
            Ws[kq + 0][row] = b.x;
            Ws[kq + 1][row] = b.y;
            Ws[kq + 2][row] = b.z;
            Ws[kq + 3][row] = b.w;
        }
        __syncthreads();

        #pragma unroll
        for (int k = 0; k < BK; k++) {
            float a[8], b[8];
            float4 a0 = *reinterpret_cast<const float4*>(&As[k][ty * 8 + 0]);
            float4 a1 = *reinterpret_cast<const float4*>(&As[k][ty * 8 + 4]);
            float4 b0 = *reinterpret_cast<const float4*>(&Ws[k][tx * 8 + 0]);
            float4 b1 = *reinterpret_cast<const float4*>(&Ws[k][tx * 8 + 4]);
            a[0]=a0.x; a[1]=a0.y; a[2]=a0.z; a[3]=a0.w;
            a[4]=a1.x; a[5]=a1.y; a[6]=a1.z; a[7]=a1.w;
            b[0]=b0.x; b[1]=b0.y; b[2]=b0.z; b[3]=b0.w;
            b[4]=b1.x; b[5]=b1.y; b[6]=b1.z; b[7]=b1.w;
            #pragma unroll
            for (int i = 0; i < 8; i++)
                #pragma unroll
                for (int j = 0; j < 8; j++)
                    acc[i][j] = fmaf(a[i], b[j], acc[i][j]);
        }
        __syncthreads();
    }

    float rw[8], wl[8], bb[8];
    #pragma unroll
    for (int i = 0; i < 8; i++) rw[i] = rew[mBase + ty * 8 + i];
    #pragma unroll
    for (int j = 0; j < 8; j++) {
        int n = nBase + tx * 8 + j;
        wl[j] = w_ih[(size_t)n * 2049 + 2048];
        bb[j] = b_ih[n];
    }
    #pragma unroll
    for (int i = 0; i < 8; i++) {
        int m = mBase + ty * 8 + i;
        #pragma unroll
        for (int j = 0; j < 8; j++) {
            int n = nBase + tx * 8 + j;
            g_gi[(size_t)m * NGATE + n] = acc[i][j] + rw[i] * wl[j] + bb[j];
        }
    }
}

// =====================================================================
// Kernel 2: persistent GRU reverse scan (R10 protocol) + two micro-opts:
//  (1) dual-issue acquire polls  -> halves observe quantization; the step
//      pace is a max over 128 CTAs, so the tail shrinks by ~an iteration
//  (2) 2-way split dot accumulators -> 16-deep FMA chains instead of 32
// =====================================================================
__device__ __forceinline__ float sigmoidf_(float x)
{
    return __fdividef(1.f, 1.f + __expf(-x));
}
__device__ __forceinline__ float tanhf_(float x)
{
    float ax = fabsf(x);
    float e  = __expf(-2.f * ax);
    float t  = __fdividef(1.f - e, 1.f + e);
    return copysignf(t, x);
}

__global__ void __launch_bounds__(256, 1) gru_scan(
    const float* __restrict__ w_hh,   // [3072, 1024]
    const float* __restrict__ b_hh,   // [3072]
    float* __restrict__ out)          // [1024]
{
    __shared__ float h_sm[HID];

    const int tid = threadIdx.x;
    const int c = blockIdx.x;
    const int w = tid >> 5;
    const int l = tid & 31;
    const int u = c * 8 + w;

    // ---- register-resident recurrent weights: lane l holds k = l + 32j ----
    float wr[32], wz[32], wn[32];
    {
        const float* pr = w_hh + (size_t)(          u) * HID + l;
        const float* pz = w_hh + (size_t)(HID     + u) * HID + l;
        const float* pn = w_hh + (size_t)(2 * HID + u) * HID + l;
        #pragma unroll
        for (int j = 0; j < 32; j++) {
            wr[j] = pr[32 * j];
            wz[j] = pz[32 * j];
            wn[j] = pn[32 * j];
        }
    }
    const float bhr = b_hh[u];
    const float bhz = b_hh[HID + u];
    const float bhn = b_hh[2 * HID + u];

    // h^0 = 0
    {
        float4 z4 = make_float4(0.f, 0.f, 0.f, 0.f);
        *reinterpret_cast<float4*>(&h_sm[tid * 4]) = z4;
    }
    float hval = 0.f;   // this warp's unit value (h_prev[u])

    unsigned* ctrp = &g_ctr;

    // prefetch gi for step 0 (t = T-1)
    const float* gp0 = g_gi + (size_t)(T_STEPS - 1) * NGATE + u;
    float gir = __ldg(gp0), giz = __ldg(gp0 + HID), gin = __ldg(gp0 + 2 * HID);

    for (int s = 0; s < T_STEPS; s++) {
        const int t = T_STEPS - 1 - s;   // reverse scan
        // prefetch NEXT step's gi now: it has the whole step to complete
        float girN = 0.f, gizN = 0.f, ginN = 0.f;
        if (s + 1 < T_STEPS) {
            const float* gp = g_gi + (size_t)(t - 1) * NGATE + u;
            girN = __ldg(gp);
            gizN = __ldg(gp + HID);
            ginN = __ldg(gp + 2 * HID);
        }

        if (s > 0) {
            if (tid == 0) {
                // dual-issue acquire-poll: two independent loads in flight
                // per iteration -> observe quantization ~halved
                const unsigned target = (unsigned)s * (unsigned)NCTA;
                unsigned f0, f1;
                do {
                    asm volatile("ld.acquire.gpu.global.u32 %0, [%2];\n\t"
                                 "ld.acquire.gpu.global.u32 %1, [%2];"
                                 : "=r"(f0), "=r"(f1) : "l"(ctrp) : "memory");
                } while (f0 < target && f1 < target);
            }
            __syncthreads();   // (A) barrier observed by all threads
            // cooperative fresh-h fetch (L2 only), 1 float4 per thread
            float4 hv4;
            asm volatile("ld.global.cg.v4.f32 {%0,%1,%2,%3}, [%4];"
                         : "=f"(hv4.x), "=f"(hv4.y), "=f"(hv4.z), "=f"(hv4.w)
                         : "l"(&g_hv[s & 1][tid * 4]) : "memory");
            *reinterpret_cast<float4*>(&h_sm[tid * 4]) = hv4;
        }
        __syncthreads();   // (B) h staged in smem

        // three 1024-dot-products, 2-way split accumulators (16-deep chains)
        float dra = 0.f, drb = 0.f, dza = 0.f, dzb = 0.f, dna = 0.f, dnb = 0.f;
        #pragma unroll
        for (int j = 0; j < 32; j += 2) {
            const float ha = h_sm[l + 32 * j];
            const float hb = h_sm[l + 32 * (j + 1)];
            dra = fmaf(wr[j],     ha, dra);
            drb = fmaf(wr[j + 1], hb, drb);
            dza = fmaf(wz[j],     ha, dza);
            dzb = fmaf(wz[j + 1], hb, dzb);
            dna = fmaf(wn[j],     ha, dna);
            dnb = fmaf(wn[j + 1], hb, dnb);
        }
        float dr = dra + drb, dz = dza + dzb, dn = dna + dnb;
        #pragma unroll
        for (int o = 16; o > 0; o >>= 1) {
            dr += __shfl_xor_sync(0xffffffffu, dr, o);
            dz += __shfl_xor_sync(0xffffffffu, dz, o);
            dn += __shfl_xor_sync(0xffffffffu, dn, o);
        }

        const float r = sigmoidf_(gir + dr + bhr);
        const float z = sigmoidf_(giz + dz + bhz);
        const float n = tanhf_(gin + r * (dn + bhn));
        hval = (1.f - z) * n + z * hval;

        if (s < T_STEPS - 1) {
            if (l == 0)
                asm volatile("st.global.cg.f32 [%0], %1;"
                             :: "l"(&g_hv[(s + 1) & 1][u]), "f"(hval) : "memory");
            __syncthreads();   // (C) all 8 unit stores issued, CTA-ordered before release
            if (tid == 0)
                asm volatile("red.release.gpu.global.add.u32 [%0], %1;"
                             :: "l"(ctrp), "r"(1u) : "memory");
        }

        gir = girN; giz = gizN; gin = ginN;
    }

    if (l == 0) out[u] = hval;
}

// =====================================================================
extern "C" void kernel_launch(void* const* d_in, const int* in_sizes, int n_in,
                              void* d_out, int out_size)
{
    const float* feat = (const float*)d_in[0];   // [8192, 2048]
    const float* rew  = (const float*)d_in[1];   // [8192]
    const float* w_ih = (const float*)d_in[2];   // [3072, 2049]
    const float* w_hh = (const float*)d_in[3];   // [3072, 1024]
    const float* b_ih = (const float*)d_in[4];   // [3072]
    const float* b_hh = (const float*)d_in[5];   // [3072]
    float* out = (float*)d_out;                  // [1, 1024]

    repack_w<<<592, 256>>>(w_ih);                // ~13us: align W for float4 loads
    dim3 ggrid(NGATE / BN, T_STEPS / BM);        // (24, 64)
    gi_gemm<<<ggrid, 256>>>(feat, rew, w_ih, b_ih);
    gru_scan<<<NCTA, 256>>>(w_hh, b_hh, out);
}

// round 16
// speedup vs baseline: 1.2093x; 1.1594x over previous
#include <cuda_runtime.h>
#include <cuda_bf16.h>
#include <math.h>

#define T_STEPS 8192
#define HID     1024
#define IN_K    2048
#define NGATE   3072
#define NCTA    128

// ---- device scratch (allocation-free: __device__ globals) ----
__device__ float g_gi[(size_t)T_STEPS * NGATE];          // ~100.7 MB input gates
__device__ __nv_bfloat16 g_fh[(size_t)T_STEPS * IN_K];   // 32 MB features hi
__device__ __nv_bfloat16 g_fl[(size_t)T_STEPS * IN_K];   // 32 MB features lo
__device__ __nv_bfloat16 g_wh[(size_t)NGATE * IN_K];     // 12 MB w_ih hi
__device__ __nv_bfloat16 g_wl[(size_t)NGATE * IN_K];     // 12 MB w_ih lo
__device__ float g_hv[2][HID];                            // double-buffered h
__device__ unsigned g_ctr;                                // scan step counter

// =====================================================================
// Kernel 0: bf16 hi/lo split of features and w_ih[:, :2048]; counter reset.
// =====================================================================
__global__ void prep(const float* __restrict__ feat, const float* __restrict__ w_ih)
{
    if (blockIdx.x == 0 && threadIdx.x == 0) g_ctr = 0u;
    const size_t stride = (size_t)gridDim.x * blockDim.x;
    const size_t i0 = (size_t)blockIdx.x * blockDim.x + threadIdx.x;

    const size_t nf = (size_t)T_STEPS * IN_K;
    for (size_t x = i0; x < nf; x += stride) {
        float v = feat[x];
        __nv_bfloat16 h = __float2bfloat16_rn(v);
        g_fh[x] = h;
        g_fl[x] = __float2bfloat16_rn(v - __bfloat162float(h));
    }
    const size_t nw = (size_t)NGATE * IN_K;
    for (size_t x = i0; x < nw; x += stride) {
        const size_t n = x >> 11;           // / 2048
        const size_t k = x & 2047;          // % 2048
        float v = w_ih[n * 2049 + k];
        __nv_bfloat16 h = __float2bfloat16_rn(v);
        g_wh[x] = h;
        g_wl[x] = __float2bfloat16_rn(v - __bfloat162float(h));
    }
}

// =====================================================================
// Kernel 1: gi = feat @ w^T via bf16-split mma.sync (3 passes: hi*hi +
// hi*lo + lo*hi, fp32 accum) + exact fp32 epilogue (reward col + bias).
// BM=BN=128, BK=32; 8 warps in 2(m)x4(n), warp tile 64x32, m16n8k16.
// Smem rows padded to 40 bf16 -> conflict-free b32 fragment loads.
// =====================================================================
#define BM 128
#define BN 128
#define BK 32
#define PADK 40

__device__ __forceinline__ void mma_bf16(float* d, const unsigned* a, const unsigned* b)
{
    asm volatile(
        "mma.sync.aligned.m16n8k16.row.col.f32.bf16.bf16.f32 "
        "{%0,%1,%2,%3}, {%4,%5,%6,%7}, {%8,%9}, {%0,%1,%2,%3};"
        : "+f"(d[0]), "+f"(d[1]), "+f"(d[2]), "+f"(d[3])
        : "r"(a[0]), "r"(a[1]), "r"(a[2]), "r"(a[3]), "r"(b[0]), "r"(b[1]));
}

__global__ void __launch_bounds__(256, 2) gi_gemm(
    const float* __restrict__ rew,    // [8192]
    const float* __restrict__ w_ih,   // [3072, 2049] (col 2048 + epilogue)
    const float* __restrict__ b_ih)   // [3072]
{
    __shared__ __align__(16) __nv_bfloat16 sAh[BM * PADK];
    __shared__ __align__(16) __nv_bfloat16 sAl[BM * PADK];
    __shared__ __align__(16) __nv_bfloat16 sWh[BN * PADK];
    __shared__ __align__(16) __nv_bfloat16 sWl[BN * PADK];

    const int tid   = threadIdx.x;
    const int nBase = blockIdx.x * BN;
    const int mBase = blockIdx.y * BM;
    const int warp  = tid >> 5;
    const int lane  = tid & 31;
    const int wm    = warp >> 2;          // 0..1
    const int wn    = warp & 3;           // 0..3
    const int g     = lane >> 2;          // group 0..7
    const int tig   = lane & 3;           // 0..3

    float acc[4][4][4];
    #pragma unroll
    for (int i = 0; i < 4; i++)
        #pragma unroll
        for (int j = 0; j < 4; j++)
            #pragma unroll
            for (int q = 0; q < 4; q++) acc[i][j][q] = 0.f;

    // per-thread tile-load coords: f = tid + v*256; r = f>>2 (row), c = f&3 (16B chunk)
    for (int kB = 0; kB < IN_K; kB += BK) {
        #pragma unroll
        for (int v = 0; v < 2; v++) {
            const int f = tid + v * 256;
            const int r = f >> 2;
            const int c = f & 3;
            const size_t goffA = (size_t)(mBase + r) * IN_K + kB + c * 8;
            const size_t goffW = (size_t)(nBase + r) * IN_K + kB + c * 8;
            const int soff = r * PADK + c * 8;
            *reinterpret_cast<uint4*>(&sAh[soff]) = *reinterpret_cast<const uint4*>(&g_fh[goffA]);
            *reinterpret_cast<uint4*>(&sAl[soff]) = *reinterpret_cast<const uint4*>(&g_fl[goffA]);
            *reinterpret_cast<uint4*>(&sWh[soff]) = *reinterpret_cast<const uint4*>(&g_wh[goffW]);
            *reinterpret_cast<uint4*>(&sWl[soff]) = *reinterpret_cast<const uint4*>(&g_wl[goffW]);
        }
        __syncthreads();

        #pragma unroll
        for (int ks = 0; ks < 2; ks++) {
            const int kofs = ks * 16;
            // A fragments (hi & lo) for all 4 m-tiles
            unsigned ah[4][4], al[4][4];
            #pragma unroll
            for (int mt = 0; mt < 4; mt++) {
                const int r0 = (wm * 64 + mt * 16 + g) * PADK + kofs + tig * 2;
                const int r1 = r0 + 8 * PADK;
                ah[mt][0] = *reinterpret_cast<const unsigned*>(&sAh[r0]);
                ah[mt][1] = *reinterpret_cast<const unsigned*>(&sAh[r1]);
                ah[mt][2] = *reinterpret_cast<const unsigned*>(&sAh[r0 + 8]);
                ah[mt][3] = *reinterpret_cast<const unsigned*>(&sAh[r1 + 8]);
                al[mt][0] = *reinterpret_cast<const unsigned*>(&sAl[r0]);
                al[mt][1] = *reinterpret_cast<const unsigned*>(&sAl[r1]);
                al[mt][2] = *reinterpret_cast<const unsigned*>(&sAl[r0 + 8]);
                al[mt][3] = *reinterpret_cast<const unsigned*>(&sAl[r1 + 8]);
            }
            #pragma unroll
            for (int nt = 0; nt < 4; nt++) {
                const int nr = (wn * 32 + nt * 8 + g) * PADK + kofs + tig * 2;
                unsigned bh[2], bl[2];
                bh[0] = *reinterpret_cast<const unsigned*>(&sWh[nr]);
                bh[1] = *reinterpret_cast<const unsigned*>(&sWh[nr + 8]);
                bl[0] = *reinterpret_cast<const unsigned*>(&sWl[nr]);
                bl[1] = *reinterpret_cast<const unsigned*>(&sWl[nr + 8]);
                #pragma unroll
                for (int mt = 0; mt < 4; mt++) {
                    mma_bf16(acc[mt][nt], ah[mt], bh);   // hi*hi
                    mma_bf16(acc[mt][nt], ah[mt], bl);   // hi*lo
                    mma_bf16(acc[mt][nt], al[mt], bh);   // lo*hi
                }
            }
        }
        __syncthreads();
    }

    // fp32 epilogue: + rew[m]*w_ih[n][2048] + b_ih[n]; pairwise n stores
    #pragma unroll
    for (int mt = 0; mt < 4; mt++) {
        #pragma unroll
        for (int half = 0; half < 2; half++) {
            const int m = mBase + wm * 64 + mt * 16 + g + half * 8;
            const float rv = __ldg(&rew[m]);
            #pragma unroll
            for (int nt = 0; nt < 4; nt++) {
                const int n = nBase + wn * 32 + nt * 8 + tig * 2;
                const float wl0 = __ldg(&w_ih[(size_t)n * 2049 + 2048]);
                const float wl1 = __ldg(&w_ih[(size_t)(n + 1) * 2049 + 2048]);
                const float bb0 = __ldg(&b_ih[n]);
                const float bb1 = __ldg(&b_ih[n + 1]);
                float2 o;
                o.x = acc[mt][nt][half * 2 + 0] + rv * wl0 + bb0;
                o.y = acc[mt][nt][half * 2 + 1] + rv * wl1 + bb1;
                *reinterpret_cast<float2*>(&g_gi[(size_t)m * NGATE + n]) = o;
            }
        }
    }
}

// =====================================================================
// Kernel 2: persistent GRU reverse scan — EXACT R10 (best known).
// =====================================================================
__device__ __forceinline__ float sigmoidf_(float x)
{
    return __fdividef(1.f, 1.f + __expf(-x));
}
__device__ __forceinline__ float tanhf_(float x)
{
    float ax = fabsf(x);
    float e  = __expf(-2.f * ax);
    float t  = __fdividef(1.f - e, 1.f + e);
    return copysignf(t, x);
}

__global__ void __launch_bounds__(256, 1) gru_scan(
    const float* __restrict__ w_hh,   // [3072, 1024]
    const float* __restrict__ b_hh,   // [3072]
    float* __restrict__ out)          // [1024]
{
    __shared__ float h_sm[HID];

    const int tid = threadIdx.x;
    const int c = blockIdx.x;
    const int w = tid >> 5;
    const int l = tid & 31;
    const int u = c * 8 + w;

    float wr[32], wz[32], wn[32];
    {
        const float* pr = w_hh + (size_t)(          u) * HID + l;
        const float* pz = w_hh + (size_t)(HID     + u) * HID + l;
        const float* pn = w_hh + (size_t)(2 * HID + u) * HID + l;
        #pragma unroll
        for (int j = 0; j < 32; j++) {
            wr[j] = pr[32 * j];
            wz[j] = pz[32 * j];
            wn[j] = pn[32 * j];
        }
    }
    const float bhr = b_hh[u];
    const float bhz = b_hh[HID + u];
    const float bhn = b_hh[2 * HID + u];

    {
        float4 z4 = make_float4(0.f, 0.f, 0.f, 0.f);
        *reinterpret_cast<float4*>(&h_sm[tid * 4]) = z4;
    }
    float hval = 0.f;

    unsigned* ctrp = &g_ctr;

    const float* gp0 = g_gi + (size_t)(T_STEPS - 1) * NGATE + u;
    float gir = __ldg(gp0), giz = __ldg(gp0 + HID), gin = __ldg(gp0 + 2 * HID);

    for (int s = 0; s < T_STEPS; s++) {
        const int t = T_STEPS - 1 - s;
        float girN = 0.f, gizN = 0.f, ginN = 0.f;
        if (s + 1 < T_STEPS) {
            const float* gp = g_gi + (size_t)(t - 1) * NGATE + u;
            girN = __ldg(gp);
            gizN = __ldg(gp + HID);
            ginN = __ldg(gp + 2 * HID);
        }

        if (s > 0) {
            if (tid == 0) {
                const unsigned target = (unsigned)s * (unsigned)NCTA;
                unsigned f;
                do {
                    asm volatile("ld.acquire.gpu.global.u32 %0, [%1];"
                                 : "=r"(f) : "l"(ctrp) : "memory");
                } while (f < target);
            }
            __syncthreads();
            float4 hv4;
            asm volatile("ld.global.cg.v4.f32 {%0,%1,%2,%3}, [%4];"
                         : "=f"(hv4.x), "=f"(hv4.y), "=f"(hv4.z), "=f"(hv4.w)
                         : "l"(&g_hv[s & 1][tid * 4]) : "memory");
            *reinterpret_cast<float4*>(&h_sm[tid * 4]) = hv4;
        }
        __syncthreads();

        float dr = 0.f, dz = 0.f, dn = 0.f;
        #pragma unroll
        for (int j = 0; j < 32; j++) {
            const float h = h_sm[l + 32 * j];
            dr = fmaf(wr[j], h, dr);
            dz = fmaf(wz[j], h, dz);
            dn = fmaf(wn[j], h, dn);
        }
        #pragma unroll
        for (int o = 16; o > 0; o >>= 1) {
            dr += __shfl_xor_sync(0xffffffffu, dr, o);
            dz += __shfl_xor_sync(0xffffffffu, dz, o);
            dn += __shfl_xor_sync(0xffffffffu, dn, o);
        }

        const float r = sigmoidf_(gir + dr + bhr);
        const float z = sigmoidf_(giz + dz + bhz);
        const float n = tanhf_(gin + r * (dn + bhn));
        hval = (1.f - z) * n + z * hval;

        if (s < T_STEPS - 1) {
            if (l == 0)
                asm volatile("st.global.cg.f32 [%0], %1;"
                             :: "l"(&g_hv[(s + 1) & 1][u]), "f"(hval) : "memory");
            __syncthreads();
            if (tid == 0)
                asm volatile("red.release.gpu.global.add.u32 [%0], %1;"
                             :: "l"(ctrp), "r"(1u) : "memory");
        }

        gir = girN; giz = gizN; gin = ginN;
    }

    if (l == 0) out[u] = hval;
}

// =====================================================================
extern "C" void kernel_launch(void* const* d_in, const int* in_sizes, int n_in,
                              void* d_out, int out_size)
{
    const float* feat = (const float*)d_in[0];   // [8192, 2048]
    const float* rew  = (const float*)d_in[1];   // [8192]
    const float* w_ih = (const float*)d_in[2];   // [3072, 2049]
    const float* w_hh = (const float*)d_in[3];   // [3072, 1024]
    const float* b_ih = (const float*)d_in[4];   // [3072]
    const float* b_hh = (const float*)d_in[5];   // [3072]
    float* out = (float*)d_out;                  // [1, 1024]

    prep<<<2048, 256>>>(feat, w_ih);             // ~25us: bf16 hi/lo splits
    dim3 ggrid(NGATE / BN, T_STEPS / BM);        // (24, 64)
    gi_gemm<<<ggrid, 256>>>(rew, w_ih, b_ih);
    gru_scan<<<NCTA, 256>>>(w_hh, b_hh, out);
}

// round 17
// speedup vs baseline: 1.2341x; 1.0205x over previous
#include <cuda_runtime.h>
#include <cuda_bf16.h>
#include <math.h>

#define T_STEPS 8192
#define HID     1024
#define IN_K    2048
#define NGATE   3072
#define NCTA    128

// ---- device scratch (allocation-free: __device__ globals) ----
__device__ float g_gi[(size_t)T_STEPS * NGATE];          // ~100.7 MB input gates
__device__ __nv_bfloat16 g_fh[(size_t)T_STEPS * IN_K];   // 32 MB features hi
__device__ __nv_bfloat16 g_fl[(size_t)T_STEPS * IN_K];   // 32 MB features lo
__device__ __nv_bfloat16 g_wh[(size_t)NGATE * IN_K];     // 12 MB w_ih hi
__device__ __nv_bfloat16 g_wl[(size_t)NGATE * IN_K];     // 12 MB w_ih lo
__device__ float g_hv[2][HID];                            // double-buffered h
__device__ unsigned g_ctr;                                // scan step counter

// =====================================================================
// Kernel 0: bf16 hi/lo split of features and w_ih[:, :2048]; counter reset.
// =====================================================================
__global__ void prep(const float* __restrict__ feat, const float* __restrict__ w_ih)
{
    if (blockIdx.x == 0 && threadIdx.x == 0) g_ctr = 0u;
    const size_t stride = (size_t)gridDim.x * blockDim.x;
    const size_t i0 = (size_t)blockIdx.x * blockDim.x + threadIdx.x;

    const size_t nf = (size_t)T_STEPS * IN_K;
    for (size_t x = i0; x < nf; x += stride) {
        float v = feat[x];
        __nv_bfloat16 h = __float2bfloat16_rn(v);
        g_fh[x] = h;
        g_fl[x] = __float2bfloat16_rn(v - __bfloat162float(h));
    }
    const size_t nw = (size_t)NGATE * IN_K;
    for (size_t x = i0; x < nw; x += stride) {
        const size_t n = x >> 11;           // / 2048
        const size_t k = x & 2047;          // % 2048
        float v = w_ih[n * 2049 + k];
        __nv_bfloat16 h = __float2bfloat16_rn(v);
        g_wh[x] = h;
        g_wl[x] = __float2bfloat16_rn(v - __bfloat162float(h));
    }
}

// =====================================================================
// Kernel 1: gi = feat @ w^T via bf16-split mma.sync (hi*hi + hi*lo +
// lo*hi, fp32 accum) + exact fp32 epilogue. NOW SOFTWARE-PIPELINED:
// double-buffered smem stages filled by 16B cp.async.cg, overlapped
// with the MMA work of the previous k-slab; ONE barrier per slab.
// BM=BN=128, BK=32; 8 warps 2(m)x4(n), warp tile 64x32, m16n8k16.
// Smem rows padded to 40 bf16 -> conflict-free b32 fragment loads.
// =====================================================================
#define BM 128
#define BN 128
#define BK 32
#define PADK 40
#define NSLAB (IN_K / BK)

__device__ __forceinline__ void mma_bf16(float* d, const unsigned* a, const unsigned* b)
{
    asm volatile(
        "mma.sync.aligned.m16n8k16.row.col.f32.bf16.bf16.f32 "
        "{%0,%1,%2,%3}, {%4,%5,%6,%7}, {%8,%9}, {%0,%1,%2,%3};"
        : "+f"(d[0]), "+f"(d[1]), "+f"(d[2]), "+f"(d[3])
        : "r"(a[0]), "r"(a[1]), "r"(a[2]), "r"(a[3]), "r"(b[0]), "r"(b[1]));
}

__device__ __forceinline__ void cpasync16(void* smem, const void* gmem)
{
    unsigned s = (unsigned)__cvta_generic_to_shared(smem);
    asm volatile("cp.async.cg.shared.global [%0], [%1], 16;"
                 :: "r"(s), "l"(gmem) : "memory");
}

__global__ void __launch_bounds__(256, 2) gi_gemm(
    const float* __restrict__ rew,    // [8192]
    const float* __restrict__ w_ih,   // [3072, 2049] (col 2048 + epilogue)
    const float* __restrict__ b_ih)   // [3072]
{
    __shared__ __align__(16) __nv_bfloat16 sAh[2][BM * PADK];
    __shared__ __align__(16) __nv_bfloat16 sAl[2][BM * PADK];
    __shared__ __align__(16) __nv_bfloat16 sWh[2][BN * PADK];
    __shared__ __align__(16) __nv_bfloat16 sWl[2][BN * PADK];

    const int tid   = threadIdx.x;
    const int nBase = blockIdx.x * BN;
    const int mBase = blockIdx.y * BM;
    const int warp  = tid >> 5;
    const int lane  = tid & 31;
    const int wm    = warp >> 2;          // 0..1
    const int wn    = warp & 3;           // 0..3
    const int g     = lane >> 2;          // group 0..7
    const int tig   = lane & 3;           // 0..3

    // per-thread tile-load coords (fixed across slabs)
    const int lr = tid >> 2;              // row 0..63 (+64 for v=1)
    const int lc = tid & 3;               // 16B chunk

    float acc[4][4][4];
    #pragma unroll
    for (int i = 0; i < 4; i++)
        #pragma unroll
        for (int j = 0; j < 4; j++)
            #pragma unroll
            for (int q = 0; q < 4; q++) acc[i][j][q] = 0.f;

    // ---- prologue: stage 0 ----
    {
        const int kB = 0;
        #pragma unroll
        for (int v = 0; v < 2; v++) {
            const int r = lr + v * 64;
            const size_t goffA = (size_t)(mBase + r) * IN_K + kB + lc * 8;
            const size_t goffW = (size_t)(nBase + r) * IN_K + kB + lc * 8;
            const int soff = r * PADK + lc * 8;
            cpasync16(&sAh[0][soff], &g_fh[goffA]);
            cpasync16(&sAl[0][soff], &g_fl[goffA]);
            cpasync16(&sWh[0][soff], &g_wh[goffW]);
            cpasync16(&sWl[0][soff], &g_wl[goffW]);
        }
        asm volatile("cp.async.commit_group;" ::: "memory");
    }

    for (int i = 0; i < NSLAB; i++) {
        asm volatile("cp.async.wait_group 0;" ::: "memory");
        __syncthreads();   // stage i resident; all threads past compute(i-1)

        if (i + 1 < NSLAB) {
            const int kB = (i + 1) * BK;
            const int b  = (i + 1) & 1;
            #pragma unroll
            for (int v = 0; v < 2; v++) {
                const int r = lr + v * 64;
                const size_t goffA = (size_t)(mBase + r) * IN_K + kB + lc * 8;
                const size_t goffW = (size_t)(nBase + r) * IN_K + kB + lc * 8;
                const int soff = r * PADK + lc * 8;
                cpasync16(&sAh[b][soff], &g_fh[goffA]);
                cpasync16(&sAl[b][soff], &g_fl[goffA]);
                cpasync16(&sWh[b][soff], &g_wh[goffW]);
                cpasync16(&sWl[b][soff], &g_wl[goffW]);
            }
            asm volatile("cp.async.commit_group;" ::: "memory");
        }

        const int cur = i & 1;
        #pragma unroll
        for (int ks = 0; ks < 2; ks++) {
            const int kofs = ks * 16;
            unsigned ah[4][4], al[4][4];
            #pragma unroll
            for (int mt = 0; mt < 4; mt++) {
                const int r0 = (wm * 64 + mt * 16 + g) * PADK + kofs + tig * 2;
                const int r1 = r0 + 8 * PADK;
                ah[mt][0] = *reinterpret_cast<const unsigned*>(&sAh[cur][r0]);
                ah[mt][1] = *reinterpret_cast<const unsigned*>(&sAh[cur][r1]);
                ah[mt][2] = *reinterpret_cast<const unsigned*>(&sAh[cur][r0 + 8]);
                ah[mt][3] = *reinterpret_cast<const unsigned*>(&sAh[cur][r1 + 8]);
                al[mt][0] = *reinterpret_cast<const unsigned*>(&sAl[cur][r0]);
                al[mt][1] = *reinterpret_cast<const unsigned*>(&sAl[cur][r1]);
                al[mt][2] = *reinterpret_cast<const unsigned*>(&sAl[cur][r0 + 8]);
                al[mt][3] = *reinterpret_cast<const unsigned*>(&sAl[cur][r1 + 8]);
            }
            #pragma unroll
            for (int nt = 0; nt < 4; nt++) {
                const int nr = (wn * 32 + nt * 8 + g) * PADK + kofs + tig * 2;
                unsigned bh[2], bl[2];
                bh[0] = *reinterpret_cast<const unsigned*>(&sWh[cur][nr]);
                bh[1] = *reinterpret_cast<const unsigned*>(&sWh[cur][nr + 8]);
                bl[0] = *reinterpret_cast<const unsigned*>(&sWl[cur][nr]);
                bl[1] = *reinterpret_cast<const unsigned*>(&sWl[cur][nr + 8]);
                #pragma unroll
                for (int mt = 0; mt < 4; mt++) {
                    mma_bf16(acc[mt][nt], ah[mt], bh);   // hi*hi
                    mma_bf16(acc[mt][nt], ah[mt], bl);   // hi*lo
                    mma_bf16(acc[mt][nt], al[mt], bh);   // lo*hi
                }
            }
        }
    }

    // fp32 epilogue: + rew[m]*w_ih[n][2048] + b_ih[n]; pairwise n stores
    #pragma unroll
    for (int mt = 0; mt < 4; mt++) {
        #pragma unroll
        for (int half = 0; half < 2; half++) {
            const int m = mBase + wm * 64 + mt * 16 + g + half * 8;
            const float rv = __ldg(&rew[m]);
            #pragma unroll
            for (int nt = 0; nt < 4; nt++) {
                const int n = nBase + wn * 32 + nt * 8 + tig * 2;
                const float wl0 = __ldg(&w_ih[(size_t)n * 2049 + 2048]);
                const float wl1 = __ldg(&w_ih[(size_t)(n + 1) * 2049 + 2048]);
                const float bb0 = __ldg(&b_ih[n]);
                const float bb1 = __ldg(&b_ih[n + 1]);
                float2 o;
                o.x = acc[mt][nt][half * 2 + 0] + rv * wl0 + bb0;
                o.y = acc[mt][nt][half * 2 + 1] + rv * wl1 + bb1;
                *reinterpret_cast<float2*>(&g_gi[(size_t)m * NGATE + n]) = o;
            }
        }
    }
}

// =====================================================================
// Kernel 2: persistent GRU reverse scan — EXACT R10 (best known, frozen).
// =====================================================================
__device__ __forceinline__ float sigmoidf_(float x)
{
    return __fdividef(1.f, 1.f + __expf(-x));
}
__device__ __forceinline__ float tanhf_(float x)
{
    float ax = fabsf(x);
    float e  = __expf(-2.f * ax);
    float t  = __fdividef(1.f - e, 1.f + e);
    return copysignf(t, x);
}

__global__ void __launch_bounds__(256, 1) gru_scan(
    const float* __restrict__ w_hh,   // [3072, 1024]
    const float* __restrict__ b_hh,   // [3072]
    float* __restrict__ out)          // [1024]
{
    __shared__ float h_sm[HID];

    const int tid = threadIdx.x;
    const int c = blockIdx.x;
    const int w = tid >> 5;
    const int l = tid & 31;
    const int u = c * 8 + w;

    float wr[32], wz[32], wn[32];
    {
        const float* pr = w_hh + (size_t)(          u) * HID + l;
        const float* pz = w_hh + (size_t)(HID     + u) * HID + l;
        const float* pn = w_hh + (size_t)(2 * HID + u) * HID + l;
        #pragma unroll
        for (int j = 0; j < 32; j++) {
            wr[j] = pr[32 * j];
            wz[j] = pz[32 * j];
            wn[j] = pn[32 * j];
        }
    }
    const float bhr = b_hh[u];
    const float bhz = b_hh[HID + u];
    const float bhn = b_hh[2 * HID + u];

    {
        float4 z4 = make_float4(0.f, 0.f, 0.f, 0.f);
        *reinterpret_cast<float4*>(&h_sm[tid * 4]) = z4;
    }
    float hval = 0.f;

    unsigned* ctrp = &g_ctr;

    const float* gp0 = g_gi + (size_t)(T_STEPS - 1) * NGATE + u;
    float gir = __ldg(gp0), giz = __ldg(gp0 + HID), gin = __ldg(gp0 + 2 * HID);

    for (int s = 0; s < T_STEPS; s++) {
        const int t = T_STEPS - 1 - s;
        float girN = 0.f, gizN = 0.f, ginN = 0.f;
        if (s + 1 < T_STEPS) {
            const float* gp = g_gi + (size_t)(t - 1) * NGATE + u;
            girN = __ldg(gp);
            gizN = __ldg(gp + HID);
            ginN = __ldg(gp + 2 * HID);
        }

        if (s > 0) {
            if (tid == 0) {
                const unsigned target = (unsigned)s * (unsigned)NCTA;
                unsigned f;
                do {
                    asm volatile("ld.acquire.gpu.global.u32 %0, [%1];"
                                 : "=r"(f) : "l"(ctrp) : "memory");
                } while (f < target);
            }
            __syncthreads();
            float4 hv4;
            asm volatile("ld.global.cg.v4.f32 {%0,%1,%2,%3}, [%4];"
                         : "=f"(hv4.x), "=f"(hv4.y), "=f"(hv4.z), "=f"(hv4.w)
                         : "l"(&g_hv[s & 1][tid * 4]) : "memory");
            *reinterpret_cast<float4*>(&h_sm[tid * 4]) = hv4;
        }
        __syncthreads();

        float dr = 0.f, dz = 0.f, dn = 0.f;
        #pragma unroll
        for (int j = 0; j < 32; j++) {
            const float h = h_sm[l + 32 * j];
            dr = fmaf(wr[j], h, dr);
            dz = fmaf(wz[j], h, dz);
            dn = fmaf(wn[j], h, dn);
        }
        #pragma unroll
        for (int o = 16; o > 0; o >>= 1) {
            dr += __shfl_xor_sync(0xffffffffu, dr, o);
            dz += __shfl_xor_sync(0xffffffffu, dz, o);
            dn += __shfl_xor_sync(0xffffffffu, dn, o);
        }

        const float r = sigmoidf_(gir + dr + bhr);
        const float z = sigmoidf_(giz + dz + bhz);
        const float n = tanhf_(gin + r * (dn + bhn));
        hval = (1.f - z) * n + z * hval;

        if (s < T_STEPS - 1) {
            if (l == 0)
                asm volatile("st.global.cg.f32 [%0], %1;"
                             :: "l"(&g_hv[(s + 1) & 1][u]), "f"(hval) : "memory");
            __syncthreads();
            if (tid == 0)
                asm volatile("red.release.gpu.global.add.u32 [%0], %1;"
                             :: "l"(ctrp), "r"(1u) : "memory");
        }

        gir = girN; giz = gizN; gin = ginN;
    }

    if (l == 0) out[u] = hval;
}

// =====================================================================
extern "C" void kernel_launch(void* const* d_in, const int* in_sizes, int n_in,
                              void* d_out, int out_size)
{
    const float* feat = (const float*)d_in[0];   // [8192, 2048]
    const float* rew  = (const float*)d_in[1];   // [8192]
    const float* w_ih = (const float*)d_in[2];   // [3072, 2049]
    const float* w_hh = (const float*)d_in[3];   // [3072, 1024]
    const float* b_ih = (const float*)d_in[4];   // [3072]
    const float* b_hh = (const float*)d_in[5];   // [3072]
    float* out = (float*)d_out;                  // [1, 1024]

    prep<<<2048, 256>>>(feat, w_ih);             // ~62us: bf16 hi/lo splits
    dim3 ggrid(NGATE / BN, T_STEPS / BM);        // (24, 64)
    gi_gemm<<<ggrid, 256>>>(rew, w_ih, b_ih);
    gru_scan<<<NCTA, 256>>>(w_hh, b_hh, out);
}